// round 15
// baseline (speedup 1.0000x reference)
#include <cuda_runtime.h>
#include <cuda_fp16.h>
#include <cstdint>

// Problem constants (fixed by setup_inputs)
#define B_   4
#define S_   2048
#define E_   1024
#define H_   16
#define D_   64
#define M_   (B_ * S_)   // 8192 rows

// Scratch (no allocation allowed). All fp16 (11-bit significand == tf32).
__device__ __half g_X[M_ * E_];
__device__ __half g_Wq[E_ * E_];
__device__ __half g_Wk[E_ * E_];
__device__ __half g_Wv[E_ * E_];
__device__ __half g_Wp[E_ * E_];
__device__ __half g_Q[M_ * E_];
__device__ __half g_K[M_ * E_];
__device__ __half g_Vt[E_ * M_];   // TRANSPOSED: [n = h*64+d][m = b*2048+s]
__device__ __half g_O[M_ * E_];

// Single extern shared declaration for the whole TU.
extern __shared__ uint32_t smem_u32[];

// ---------------------------------------------------------------------------
// helpers
// ---------------------------------------------------------------------------
__device__ __forceinline__ uint32_t h2u(__half2 h) { return *(uint32_t*)&h; }

__device__ __forceinline__ void mma_f16(float& d0, float& d1, float& d2, float& d3,
                                        uint32_t a0, uint32_t a1, uint32_t a2, uint32_t a3,
                                        uint32_t b0, uint32_t b1) {
    asm volatile(
        "mma.sync.aligned.m16n8k16.row.col.f32.f16.f16.f32 "
        "{%0,%1,%2,%3}, {%4,%5,%6,%7}, {%8,%9}, {%0,%1,%2,%3};\n"
        : "+f"(d0), "+f"(d1), "+f"(d2), "+f"(d3)
        : "r"(a0), "r"(a1), "r"(a2), "r"(a3), "r"(b0), "r"(b1));
}

__device__ __forceinline__ void cp16(void* dst_smem, const void* src_gmem) {
    uint32_t d = (uint32_t)__cvta_generic_to_shared(dst_smem);
    asm volatile("cp.async.cg.shared.global [%0], [%1], 16;\n"
                 :: "r"(d), "l"(src_gmem));
}
#define CP_COMMIT()  asm volatile("cp.async.commit_group;\n" ::: "memory")
#define CP_WAIT(n)   asm volatile("cp.async.wait_group %0;\n" :: "n"(n) : "memory")

// ---------------------------------------------------------------------------
// prepass (single launch): round X and the 4 weights to fp16.
// ---------------------------------------------------------------------------
#define NX4  ((M_ * E_) / 4)
#define NW4  ((E_ * E_) / 4)
#define NTOT (NX4 + 4 * NW4)

__global__ void round_all_k(const float* __restrict__ X,
                            const float* __restrict__ W0, const float* __restrict__ W1,
                            const float* __restrict__ W2, const float* __restrict__ W3,
                            __half* __restrict__ dX,
                            __half* __restrict__ dW0, __half* __restrict__ dW1,
                            __half* __restrict__ dW2, __half* __restrict__ dW3) {
    const int i = blockIdx.x * blockDim.x + threadIdx.x;
    if (i >= NTOT) return;
    const float4* src;
    __half* dstb;
    int off;
    if (i < NX4) {
        src = (const float4*)X; dstb = dX; off = i;
    } else {
        const int j = i - NX4;
        const int w = j >> 18;
        off = j & (NW4 - 1);
        const float4* s[4] = {(const float4*)W0, (const float4*)W1,
                              (const float4*)W2, (const float4*)W3};
        __half* d[4] = {dW0, dW1, dW2, dW3};
        src = s[w]; dstb = d[w];
    }
    float4 v = src[off];
    uint2 u;
    u.x = h2u(__floats2half2_rn(v.x, v.y));
    u.y = h2u(__floats2half2_rn(v.z, v.w));
    ((uint2*)dstb)[off] = u;
}

// ---------------------------------------------------------------------------
// Batched fp16 GEMM (5-stage pipeline): C_z[m,n] = sum_k A[m,k]*W_z[n,k].
// 128x128 block tile, BK=32 halves, 128 thr (4 warps), warp tile 64x64.
// CP_WAIT(3): three tiles in flight. One __syncthreads per k-tile.
// mode: 0 = half out (Q/K), 1 = half out TRANSPOSED (V), 2 = float out (proj).
// ---------------------------------------------------------------------------
#define SPAD 20                              // 16 pair-cols + 4 pad (uint32)
#define STAGE_W (128 * SPAD)
#define NSTAGE 5
#define GEMM_SMEM (NSTAGE * 2 * STAGE_W * 4) // 102,400 B -> 2 CTAs/SM OK

struct GemmBatch {
    const __half* W[3];
    void* C[3];
    int mode[3];
};

__global__ __launch_bounds__(128, 2)
void hgemm_batched(const __half* __restrict__ A, GemmBatch args) {
    uint32_t* As = smem_u32;                      // [5][128][SPAD]
    uint32_t* Ws = smem_u32 + NSTAGE * STAGE_W;   // [5][128][SPAD]

    const __half* __restrict__ Wg = args.W[blockIdx.z];
    const int mode = args.mode[blockIdx.z];

    const int t    = threadIdx.x;
    const int m0   = blockIdx.y * 128;
    const int n0   = blockIdx.x * 128;
    const int lane = t & 31;
    const int w    = t >> 5;
    const int g    = lane >> 2;
    const int c    = lane & 3;
    const int wm   = (w & 1) * 64;
    const int wn   = (w >> 1) * 64;

    float acc[32][4];
    #pragma unroll
    for (int i = 0; i < 32; i++)
        #pragma unroll
        for (int j = 0; j < 4; j++) acc[i][j] = 0.f;

    const int NT = E_ / 32;                  // 32 k-tiles

    auto issue = [&](int kt, int bufi) {
        const int koff = kt * 32;            // halves
        uint32_t* Ab = As + bufi * STAGE_W;
        uint32_t* Wb = Ws + bufi * STAGE_W;
        #pragma unroll
        for (int i = 0; i < 4; i++) {
            const int idx = i * 128 + t;     // 0..511
            const int r   = idx >> 2;        // 0..127
            const int c16 = idx & 3;         // 0..3 (16B seg = 8 halves)
            cp16(&Ab[r * SPAD + c16 * 4], A  + (long)(m0 + r) * E_ + koff + c16 * 8);
            cp16(&Wb[r * SPAD + c16 * 4], Wg + (long)(n0 + r) * E_ + koff + c16 * 8);
        }
        CP_COMMIT();
    };

    issue(0, 0);
    issue(1, 1);
    issue(2, 2);
    issue(3, 3);

    int buf = 0;
    for (int kt = 0; kt < NT; kt++) {
        const int rem = NT - 1 - kt;         // groups pending after tile kt done
        if (rem >= 3)      { CP_WAIT(3); }
        else if (rem == 2) { CP_WAIT(2); }
        else if (rem == 1) { CP_WAIT(1); }
        else               { CP_WAIT(0); }
        __syncthreads();                     // tile kt visible; buf[(kt+4)%5] free
        if (kt + 4 < NT) issue(kt + 4, (buf + 4) % NSTAGE);

        const uint32_t* Ab = As + buf * STAGE_W;
        const uint32_t* Wb = Ws + buf * STAGE_W;

        #pragma unroll
        for (int ks = 0; ks < 2; ks++) {     // 2 x k16 per 32-half tile
            const int k0p = ks * 8;          // pair offset
            uint32_t b[8][2];
            #pragma unroll
            for (int ni = 0; ni < 8; ni++) {
                const int nb = wn + ni * 8;
                b[ni][0] = Wb[(nb + g) * SPAD + k0p + c];
                b[ni][1] = Wb[(nb + g) * SPAD + k0p + c + 4];
            }
            #pragma unroll
            for (int mi = 0; mi < 4; mi++) {
                const int mb = wm + mi * 16;
                uint32_t a0 = Ab[(mb + g) * SPAD + k0p + c];
                uint32_t a1 = Ab[(mb + g + 8) * SPAD + k0p + c];
                uint32_t a2 = Ab[(mb + g) * SPAD + k0p + c + 4];
                uint32_t a3 = Ab[(mb + g + 8) * SPAD + k0p + c + 4];
                #pragma unroll
                for (int ni = 0; ni < 8; ni++) {
                    float* d = acc[mi * 8 + ni];
                    mma_f16(d[0], d[1], d[2], d[3], a0, a1, a2, a3,
                            b[ni][0], b[ni][1]);
                }
            }
        }
        buf = (buf + 1 == NSTAGE) ? 0 : buf + 1;
    }

    if (mode == 2) {
        float* C = (float*)args.C[blockIdx.z];
        #pragma unroll
        for (int mi = 0; mi < 4; mi++)
            #pragma unroll
            for (int ni = 0; ni < 8; ni++) {
                float* d = acc[mi * 8 + ni];
                const long r0 = m0 + wm + mi * 16 + g;
                const long col = n0 + wn + ni * 8 + 2 * c;
                *(float2*)(C + r0 * E_ + col)       = make_float2(d[0], d[1]);
                *(float2*)(C + (r0 + 8) * E_ + col) = make_float2(d[2], d[3]);
            }
    } else if (mode == 0) {
        __half* C = (__half*)args.C[blockIdx.z];
        #pragma unroll
        for (int mi = 0; mi < 4; mi++)
            #pragma unroll
            for (int ni = 0; ni < 8; ni++) {
                float* d = acc[mi * 8 + ni];
                const long r0 = m0 + wm + mi * 16 + g;
                const long col = n0 + wn + ni * 8 + 2 * c;
                *(uint32_t*)(C + r0 * E_ + col)       = h2u(__floats2half2_rn(d[0], d[1]));
                *(uint32_t*)(C + (r0 + 8) * E_ + col) = h2u(__floats2half2_rn(d[2], d[3]));
            }
    } else {
        // V: transpose through SMEM, write g_Vt[n][m] coalesced.
        __syncthreads();                     // mainloop smem reads done
        __half* Ts = (__half*)smem_u32;      // [128 n][136 m] halves
        #pragma unroll
        for (int mi = 0; mi < 4; mi++)
            #pragma unroll
            for (int ni = 0; ni < 8; ni++) {
                float* d = acc[mi * 8 + ni];
                const int rl = wm + mi * 16 + g;
                const int cl = wn + ni * 8 + 2 * c;
                Ts[cl * 136 + rl]           = __float2half_rn(d[0]);
                Ts[(cl + 1) * 136 + rl]     = __float2half_rn(d[1]);
                Ts[cl * 136 + rl + 8]       = __float2half_rn(d[2]);
                Ts[(cl + 1) * 136 + rl + 8] = __float2half_rn(d[3]);
            }
        __syncthreads();
        __half* Vt = (__half*)args.C[blockIdx.z];
        const int a  = t >> 6;               // 0..1
        const int b2 = t & 63;               // 0..63 (m pair index)
        #pragma unroll 8
        for (int ni2 = 0; ni2 < 64; ni2++) {
            const int nl = ni2 * 2 + a;
            uint32_t u = ((uint32_t*)(Ts + nl * 136))[b2];
            *(uint32_t*)(Vt + (long)(n0 + nl) * M_ + m0 + b2 * 2) = u;
        }
    }
}

// ---------------------------------------------------------------------------
// flash_mma: fp16 tensor-core flash attention (causal), fp32 softmax/acc.
// Block = 128 q rows, 8 warps x 16 rows. K-tiles of 64 keys, 4-stage cp.async.
// K from g_K (token-major), V from g_Vt (d-major).
// ---------------------------------------------------------------------------
#define FSTR 36                              // 32 pair-cols + 4 pad (uint32)
#define KV_STAGE (2 * 64 * FSTR)             // K + V tiles per stage
#define FNSTAGE 4
#define FLASH_SMEM ((FNSTAGE * KV_STAGE + 128 * FSTR) * 4)   // 92,160 B

__global__ __launch_bounds__(256)
void flash_mma(const __half* __restrict__ Qh, const __half* __restrict__ Kh,
               const __half* __restrict__ Vth, __half* __restrict__ O) {
    uint32_t* smem = smem_u32;
    uint32_t* Ps = smem + FNSTAGE * KV_STAGE; // [128][FSTR] (Q stage / P pairs)

    const int t    = threadIdx.x;
    const int lane = t & 31;
    const int w    = t >> 5;
    const int g    = lane >> 2;
    const int c    = lane & 3;
    const int wm   = w * 16;

    const int qt = (gridDim.x - 1) - blockIdx.x;   // LPT: longest first
    const int h  = blockIdx.y;
    const int b  = blockIdx.z;
    const int q0 = qt * 128;
    const int row0 = q0 + wm + g;
    const int row1 = row0 + 8;

    // ---- stage Q tile (cp.async group 0) ----
    {
        const __half* Qg = Qh + ((long)(b * S_ + q0)) * E_ + h * 64;
        #pragma unroll
        for (int i = 0; i < 4; i++) {
            const int idx = i * 256 + t;     // 0..1023
            const int r = idx >> 3;          // 0..127
            const int seg = idx & 7;         // 8 halves per seg
            cp16(&Ps[r * FSTR + seg * 4], Qg + (long)r * E_ + seg * 8);
        }
        CP_COMMIT();
    }

    const int ktmax = 2 * (qt + 1);

    auto issue_kv = [&](int kt, int bufi) {
        const __half* Kp = Kh + ((long)(b * S_ + kt * 64)) * E_ + h * 64;
        const __half* Vp = Vth + (long)(h * 64) * M_ + b * S_ + kt * 64;
        uint32_t* Kb = smem + bufi * KV_STAGE;
        uint32_t* Vb = Kb + 64 * FSTR;
        #pragma unroll
        for (int i = 0; i < 2; i++) {
            const int idx = i * 256 + t;     // 0..511
            const int r = idx >> 3;          // 0..63
            const int seg = idx & 7;
            cp16(&Kb[r * FSTR + seg * 4], Kp + (long)r * E_ + seg * 8);
            cp16(&Vb[r * FSTR + seg * 4], Vp + (long)r * M_ + seg * 8);
        }
        CP_COMMIT();
    };

    // prologue: up to 3 KV tiles in flight
    issue_kv(0, 0);
    if (ktmax > 1) issue_kv(1, 1);
    if (ktmax > 2) issue_kv(2, 2);

    // wait for Q (groups pending: the issued KV tiles)
    {
        const int kvp = (ktmax > 2) ? 3 : ktmax;   // issued kv groups
        if (kvp == 3)      { CP_WAIT(3); }
        else if (kvp == 2) { CP_WAIT(2); }
        else               { CP_WAIT(1); }
    }
    __syncthreads();

    // Q fragments, pre-scaled by 1/8 (exact in fp16)
    const __half2 sc2 = __float2half2_rn(0.125f);
    uint32_t qa[4][4];
    #pragma unroll
    for (int ks = 0; ks < 4; ks++) {
        #pragma unroll
        for (int j = 0; j < 4; j++) {
            const int row = wm + g + ((j & 1) ? 8 : 0);
            const int cp  = ks * 8 + c + ((j & 2) ? 4 : 0);
            uint32_t u = Ps[row * FSTR + cp];
            __half2 hv = __hmul2(*(__half2*)&u, sc2);
            qa[ks][j] = h2u(hv);
        }
    }

    float accO[8][4];
    #pragma unroll
    for (int i = 0; i < 8; i++)
        #pragma unroll
        for (int j = 0; j < 4; j++) accO[i][j] = 0.f;
    float m0v = -1e30f, m1v = -1e30f, l0 = 0.f, l1 = 0.f;

    int buf = 0;
    for (int kt = 0; kt < ktmax; kt++) {
        const int ks = kt * 64;

        const int rem = ktmax - 1 - kt;      // kv groups pending after kt done
        if (rem >= 2)      { CP_WAIT(2); }
        else if (rem == 1) { CP_WAIT(1); }
        else               { CP_WAIT(0); }
        __syncthreads();                     // tile kt visible; buf[(kt+3)%4] free
        if (kt + 3 < ktmax) issue_kv(kt + 3, (buf + 3) & 3);

        const uint32_t* Kb = smem + buf * KV_STAGE;
        const uint32_t* Vb = Kb + 64 * FSTR;

        if (ks <= q0 + wm + 15) {
            // ---- S = Q K^T ----
            float sc[8][4];
            #pragma unroll
            for (int nt = 0; nt < 8; nt++)
                #pragma unroll
                for (int j = 0; j < 4; j++) sc[nt][j] = 0.f;

            #pragma unroll
            for (int kc = 0; kc < 4; kc++) {
                #pragma unroll
                for (int nt = 0; nt < 8; nt++) {
                    uint32_t b0 = Kb[(nt * 8 + g) * FSTR + kc * 8 + c];
                    uint32_t b1 = Kb[(nt * 8 + g) * FSTR + kc * 8 + c + 4];
                    mma_f16(sc[nt][0], sc[nt][1], sc[nt][2], sc[nt][3],
                            qa[kc][0], qa[kc][1], qa[kc][2], qa[kc][3], b0, b1);
                }
            }

            // ---- causal mask (diagonal-straddling tiles only) ----
            if (ks + 63 > q0 + wm) {
                const int colbase = ks + 2 * c;
                #pragma unroll
                for (int nt = 0; nt < 8; nt++) {
                    const int col = colbase + nt * 8;
                    if (col     > row0) sc[nt][0] = -1e30f;
                    if (col + 1 > row0) sc[nt][1] = -1e30f;
                    if (col     > row1) sc[nt][2] = -1e30f;
                    if (col + 1 > row1) sc[nt][3] = -1e30f;
                }
            }

            // ---- online softmax ----
            float tm0 = -1e30f, tm1 = -1e30f;
            #pragma unroll
            for (int nt = 0; nt < 8; nt++) {
                tm0 = fmaxf(tm0, fmaxf(sc[nt][0], sc[nt][1]));
                tm1 = fmaxf(tm1, fmaxf(sc[nt][2], sc[nt][3]));
            }
            tm0 = fmaxf(tm0, __shfl_xor_sync(0xffffffff, tm0, 1));
            tm0 = fmaxf(tm0, __shfl_xor_sync(0xffffffff, tm0, 2));
            tm1 = fmaxf(tm1, __shfl_xor_sync(0xffffffff, tm1, 1));
            tm1 = fmaxf(tm1, __shfl_xor_sync(0xffffffff, tm1, 2));

            const float mn0 = fmaxf(m0v, tm0);
            const float mn1 = fmaxf(m1v, tm1);
            const float corr0 = __expf(m0v - mn0);
            const float corr1 = __expf(m1v - mn1);

            float ls0 = 0.f, ls1 = 0.f;
            #pragma unroll
            for (int nt = 0; nt < 8; nt++) {
                sc[nt][0] = __expf(sc[nt][0] - mn0);
                sc[nt][1] = __expf(sc[nt][1] - mn0);
                sc[nt][2] = __expf(sc[nt][2] - mn1);
                sc[nt][3] = __expf(sc[nt][3] - mn1);
                ls0 += sc[nt][0] + sc[nt][1];
                ls1 += sc[nt][2] + sc[nt][3];
            }
            ls0 += __shfl_xor_sync(0xffffffff, ls0, 1);
            ls0 += __shfl_xor_sync(0xffffffff, ls0, 2);
            ls1 += __shfl_xor_sync(0xffffffff, ls1, 1);
            ls1 += __shfl_xor_sync(0xffffffff, ls1, 2);

            l0 = l0 * corr0 + ls0;
            l1 = l1 * corr1 + ls1;
            m0v = mn0; m1v = mn1;

            #pragma unroll
            for (int nt = 0; nt < 8; nt++) {
                accO[nt][0] *= corr0; accO[nt][1] *= corr0;
                accO[nt][2] *= corr1; accO[nt][3] *= corr1;
            }

            // ---- P -> half2 pairs in smem (warp-private rows) ----
            __syncwarp();
            #pragma unroll
            for (int nt = 0; nt < 8; nt++) {
                Ps[(wm + g) * FSTR + nt * 4 + c]     = h2u(__floats2half2_rn(sc[nt][0], sc[nt][1]));
                Ps[(wm + g + 8) * FSTR + nt * 4 + c] = h2u(__floats2half2_rn(sc[nt][2], sc[nt][3]));
            }
            __syncwarp();

            // ---- O += P V  (V^T tiles: rows = d, pair-cols = keys) ----
            #pragma unroll
            for (int kc = 0; kc < 4; kc++) {
                uint32_t a0 = Ps[(wm + g) * FSTR + kc * 8 + c];
                uint32_t a1 = Ps[(wm + g + 8) * FSTR + kc * 8 + c];
                uint32_t a2 = Ps[(wm + g) * FSTR + kc * 8 + c + 4];
                uint32_t a3 = Ps[(wm + g + 8) * FSTR + kc * 8 + c + 4];
                #pragma unroll
                for (int nt = 0; nt < 8; nt++) {
                    uint32_t b0 = Vb[(nt * 8 + g) * FSTR + kc * 8 + c];
                    uint32_t b1 = Vb[(nt * 8 + g) * FSTR + kc * 8 + c + 4];
                    mma_f16(accO[nt][0], accO[nt][1], accO[nt][2], accO[nt][3],
                            a0, a1, a2, a3, b0, b1);
                }
            }
        }
        buf = (buf + 1) & 3;
    }

    // ---- epilogue: O as fp16 (feeds final GEMM) ----
    const float inv0 = 1.f / l0;
    const float inv1 = 1.f / l1;
    __half* O0 = O + ((long)(b * S_ + row0)) * E_ + h * 64;
    __half* O1 = O + ((long)(b * S_ + row1)) * E_ + h * 64;
    #pragma unroll
    for (int nt = 0; nt < 8; nt++) {
        *(uint32_t*)(O0 + nt * 8 + 2 * c) =
            h2u(__floats2half2_rn(accO[nt][0] * inv0, accO[nt][1] * inv0));
        *(uint32_t*)(O1 + nt * 8 + 2 * c) =
            h2u(__floats2half2_rn(accO[nt][2] * inv1, accO[nt][3] * inv1));
    }
}

// ---------------------------------------------------------------------------
// Launch
// ---------------------------------------------------------------------------
extern "C" void kernel_launch(void* const* d_in, const int* in_sizes, int n_in,
                              void* d_out, int out_size) {
    const float* X  = nullptr;
    const float* Wm[4] = {nullptr, nullptr, nullptr, nullptr};
    int wcount = 0;
    for (int i = 0; i < n_in; i++) {
        const long sz = in_sizes[i];
        if (sz == (long)M_ * E_) {
            X = (const float*)d_in[i];
        } else if (sz == (long)E_ * E_) {
            if (wcount < 4) Wm[wcount++] = (const float*)d_in[i];
        }
    }
    float* out = (float*)d_out;

    __half *Xp, *Wqp, *Wkp, *Wvp, *Wpp, *Qp, *Kp, *Vtp, *Op;
    cudaGetSymbolAddress((void**)&Xp,  g_X);
    cudaGetSymbolAddress((void**)&Wqp, g_Wq);
    cudaGetSymbolAddress((void**)&Wkp, g_Wk);
    cudaGetSymbolAddress((void**)&Wvp, g_Wv);
    cudaGetSymbolAddress((void**)&Wpp, g_Wp);
    cudaGetSymbolAddress((void**)&Qp,  g_Q);
    cudaGetSymbolAddress((void**)&Kp,  g_K);
    cudaGetSymbolAddress((void**)&Vtp, g_Vt);
    cudaGetSymbolAddress((void**)&Op,  g_O);

    cudaFuncSetAttribute(hgemm_batched,
                         cudaFuncAttributeMaxDynamicSharedMemorySize, GEMM_SMEM);
    cudaFuncSetAttribute(flash_mma,
                         cudaFuncAttributeMaxDynamicSharedMemorySize, FLASH_SMEM);

    // Prepass (1 launch): round all inputs to fp16.
    round_all_k<<<(NTOT + 255) / 256, 256>>>(X, Wm[0], Wm[1], Wm[2], Wm[3],
                                             Xp, Wqp, Wkp, Wvp, Wpp);

    // Fused Q/K/V projections. V written transposed.
    GemmBatch qkv;
    qkv.W[0] = Wqp; qkv.W[1] = Wkp; qkv.W[2] = Wvp;
    qkv.C[0] = Qp;  qkv.C[1] = Kp;  qkv.C[2] = Vtp;
    qkv.mode[0] = 0; qkv.mode[1] = 0; qkv.mode[2] = 1;
    dim3 qkvGrid(E_ / 128, M_ / 128, 3);   // (8, 64, 3)
    hgemm_batched<<<qkvGrid, 128, GEMM_SMEM>>>(Xp, qkv);

    // Attention
    dim3 fGrid(S_ / 128, H_, B_);          // (16, 16, 4)
    flash_mma<<<fGrid, 256, FLASH_SMEM>>>(Qp, Kp, Vtp, Op);

    // Output projection (fp32 out)
    GemmBatch proj;
    proj.W[0] = Wpp; proj.W[1] = Wpp; proj.W[2] = Wpp;
    proj.C[0] = out; proj.C[1] = out; proj.C[2] = out;
    proj.mode[0] = 2; proj.mode[1] = 2; proj.mode[2] = 2;
    dim3 pGrid(E_ / 128, M_ / 128, 1);
    hgemm_batched<<<pGrid, 128, GEMM_SMEM>>>(Op, proj);
}

// round 16
// speedup vs baseline: 1.0243x; 1.0243x over previous
#include <cuda_runtime.h>
#include <cuda_fp16.h>
#include <cstdint>

// Problem constants (fixed by setup_inputs)
#define B_   4
#define S_   2048
#define E_   1024
#define H_   16
#define D_   64
#define M_   (B_ * S_)   // 8192 rows

// Scratch (no allocation allowed). All fp16 (11-bit significand == tf32).
__device__ __half g_X[M_ * E_];
__device__ __half g_Wq[E_ * E_];
__device__ __half g_Wk[E_ * E_];
__device__ __half g_Wv[E_ * E_];
__device__ __half g_Wp[E_ * E_];
__device__ __half g_Q[M_ * E_];
__device__ __half g_K[M_ * E_];
__device__ __half g_Vt[E_ * M_];   // TRANSPOSED: [n = h*64+d][m = b*2048+s]
__device__ __half g_O[M_ * E_];

// Single extern shared declaration for the whole TU.
extern __shared__ uint32_t smem_u32[];

// ---------------------------------------------------------------------------
// helpers
// ---------------------------------------------------------------------------
__device__ __forceinline__ uint32_t h2u(__half2 h) { return *(uint32_t*)&h; }

__device__ __forceinline__ void mma_f16(float& d0, float& d1, float& d2, float& d3,
                                        uint32_t a0, uint32_t a1, uint32_t a2, uint32_t a3,
                                        uint32_t b0, uint32_t b1) {
    asm volatile(
        "mma.sync.aligned.m16n8k16.row.col.f32.f16.f16.f32 "
        "{%0,%1,%2,%3}, {%4,%5,%6,%7}, {%8,%9}, {%0,%1,%2,%3};\n"
        : "+f"(d0), "+f"(d1), "+f"(d2), "+f"(d3)
        : "r"(a0), "r"(a1), "r"(a2), "r"(a3), "r"(b0), "r"(b1));
}

__device__ __forceinline__ void cp16(void* dst_smem, const void* src_gmem) {
    uint32_t d = (uint32_t)__cvta_generic_to_shared(dst_smem);
    asm volatile("cp.async.cg.shared.global [%0], [%1], 16;\n"
                 :: "r"(d), "l"(src_gmem));
}
#define CP_COMMIT()  asm volatile("cp.async.commit_group;\n" ::: "memory")
#define CP_WAIT(n)   asm volatile("cp.async.wait_group %0;\n" :: "n"(n) : "memory")

// ---------------------------------------------------------------------------
// prepass (single launch): round X and the 4 weights to fp16.
// ---------------------------------------------------------------------------
#define NX4  ((M_ * E_) / 4)
#define NW4  ((E_ * E_) / 4)
#define NTOT (NX4 + 4 * NW4)

__global__ void round_all_k(const float* __restrict__ X,
                            const float* __restrict__ W0, const float* __restrict__ W1,
                            const float* __restrict__ W2, const float* __restrict__ W3,
                            __half* __restrict__ dX,
                            __half* __restrict__ dW0, __half* __restrict__ dW1,
                            __half* __restrict__ dW2, __half* __restrict__ dW3) {
    const int i = blockIdx.x * blockDim.x + threadIdx.x;
    if (i >= NTOT) return;
    const float4* src;
    __half* dstb;
    int off;
    if (i < NX4) {
        src = (const float4*)X; dstb = dX; off = i;
    } else {
        const int j = i - NX4;
        const int w = j >> 18;
        off = j & (NW4 - 1);
        const float4* s[4] = {(const float4*)W0, (const float4*)W1,
                              (const float4*)W2, (const float4*)W3};
        __half* d[4] = {dW0, dW1, dW2, dW3};
        src = s[w]; dstb = d[w];
    }
    float4 v = src[off];
    uint2 u;
    u.x = h2u(__floats2half2_rn(v.x, v.y));
    u.y = h2u(__floats2half2_rn(v.z, v.w));
    ((uint2*)dstb)[off] = u;
}

// ---------------------------------------------------------------------------
// Batched fp16 GEMM (4-stage pipeline — R14 best config):
// C_z[m,n] = sum_k A[m,k]*W_z[n,k], z=blockIdx.z.
// 128x128 block tile, BK=32 halves, 128 thr (4 warps), warp tile 64x64.
// CP_WAIT(2): two tiles in flight. One __syncthreads per k-tile.
// mode: 0 = half out (Q/K), 1 = half out TRANSPOSED (V), 2 = float out (proj).
// ---------------------------------------------------------------------------
#define SPAD 20                              // 16 pair-cols + 4 pad (uint32)
#define STAGE_W (128 * SPAD)
#define NSTAGE 4
#define GEMM_SMEM (NSTAGE * 2 * STAGE_W * 4) // 81,920 B -> 2 CTAs/SM OK

struct GemmBatch {
    const __half* W[3];
    void* C[3];
    int mode[3];
};

__global__ __launch_bounds__(128, 2)
void hgemm_batched(const __half* __restrict__ A, GemmBatch args) {
    uint32_t* As = smem_u32;                      // [4][128][SPAD]
    uint32_t* Ws = smem_u32 + NSTAGE * STAGE_W;   // [4][128][SPAD]

    const __half* __restrict__ Wg = args.W[blockIdx.z];
    const int mode = args.mode[blockIdx.z];

    const int t    = threadIdx.x;
    const int m0   = blockIdx.y * 128;
    const int n0   = blockIdx.x * 128;
    const int lane = t & 31;
    const int w    = t >> 5;
    const int g    = lane >> 2;
    const int c    = lane & 3;
    const int wm   = (w & 1) * 64;
    const int wn   = (w >> 1) * 64;

    float acc[32][4];
    #pragma unroll
    for (int i = 0; i < 32; i++)
        #pragma unroll
        for (int j = 0; j < 4; j++) acc[i][j] = 0.f;

    const int NT = E_ / 32;                  // 32 k-tiles

    auto issue = [&](int kt, int bufi) {
        const int koff = kt * 32;            // halves
        uint32_t* Ab = As + bufi * STAGE_W;
        uint32_t* Wb = Ws + bufi * STAGE_W;
        #pragma unroll
        for (int i = 0; i < 4; i++) {
            const int idx = i * 128 + t;     // 0..511
            const int r   = idx >> 2;        // 0..127
            const int c16 = idx & 3;         // 0..3 (16B seg = 8 halves)
            cp16(&Ab[r * SPAD + c16 * 4], A  + (long)(m0 + r) * E_ + koff + c16 * 8);
            cp16(&Wb[r * SPAD + c16 * 4], Wg + (long)(n0 + r) * E_ + koff + c16 * 8);
        }
        CP_COMMIT();
    };

    issue(0, 0);
    issue(1, 1);
    issue(2, 2);

    int buf = 0;
    for (int kt = 0; kt < NT; kt++) {
        if (kt + 3 < NT)      { CP_WAIT(2); }
        else if (kt + 2 < NT) { CP_WAIT(1); }
        else                  { CP_WAIT(0); }
        __syncthreads();                     // tile kt visible; buf[(kt+3)%4] free
        if (kt + 3 < NT) issue(kt + 3, (buf + 3) & 3);

        const uint32_t* Ab = As + buf * STAGE_W;
        const uint32_t* Wb = Ws + buf * STAGE_W;

        #pragma unroll
        for (int ks = 0; ks < 2; ks++) {     // 2 x k16 per 32-half tile
            const int k0p = ks * 8;          // pair offset
            uint32_t b[8][2];
            #pragma unroll
            for (int ni = 0; ni < 8; ni++) {
                const int nb = wn + ni * 8;
                b[ni][0] = Wb[(nb + g) * SPAD + k0p + c];
                b[ni][1] = Wb[(nb + g) * SPAD + k0p + c + 4];
            }
            #pragma unroll
            for (int mi = 0; mi < 4; mi++) {
                const int mb = wm + mi * 16;
                uint32_t a0 = Ab[(mb + g) * SPAD + k0p + c];
                uint32_t a1 = Ab[(mb + g + 8) * SPAD + k0p + c];
                uint32_t a2 = Ab[(mb + g) * SPAD + k0p + c + 4];
                uint32_t a3 = Ab[(mb + g + 8) * SPAD + k0p + c + 4];
                #pragma unroll
                for (int ni = 0; ni < 8; ni++) {
                    float* d = acc[mi * 8 + ni];
                    mma_f16(d[0], d[1], d[2], d[3], a0, a1, a2, a3,
                            b[ni][0], b[ni][1]);
                }
            }
        }
        buf = (buf + 1) & 3;
    }

    if (mode == 2) {
        float* C = (float*)args.C[blockIdx.z];
        #pragma unroll
        for (int mi = 0; mi < 4; mi++)
            #pragma unroll
            for (int ni = 0; ni < 8; ni++) {
                float* d = acc[mi * 8 + ni];
                const long r0 = m0 + wm + mi * 16 + g;
                const long col = n0 + wn + ni * 8 + 2 * c;
                *(float2*)(C + r0 * E_ + col)       = make_float2(d[0], d[1]);
                *(float2*)(C + (r0 + 8) * E_ + col) = make_float2(d[2], d[3]);
            }
    } else if (mode == 0) {
        __half* C = (__half*)args.C[blockIdx.z];
        #pragma unroll
        for (int mi = 0; mi < 4; mi++)
            #pragma unroll
            for (int ni = 0; ni < 8; ni++) {
                float* d = acc[mi * 8 + ni];
                const long r0 = m0 + wm + mi * 16 + g;
                const long col = n0 + wn + ni * 8 + 2 * c;
                *(uint32_t*)(C + r0 * E_ + col)       = h2u(__floats2half2_rn(d[0], d[1]));
                *(uint32_t*)(C + (r0 + 8) * E_ + col) = h2u(__floats2half2_rn(d[2], d[3]));
            }
    } else {
        // V: transpose through SMEM, write g_Vt[n][m] coalesced.
        __syncthreads();                     // mainloop smem reads done
        __half* Ts = (__half*)smem_u32;      // [128 n][136 m] halves
        #pragma unroll
        for (int mi = 0; mi < 4; mi++)
            #pragma unroll
            for (int ni = 0; ni < 8; ni++) {
                float* d = acc[mi * 8 + ni];
                const int rl = wm + mi * 16 + g;
                const int cl = wn + ni * 8 + 2 * c;
                Ts[cl * 136 + rl]           = __float2half_rn(d[0]);
                Ts[(cl + 1) * 136 + rl]     = __float2half_rn(d[1]);
                Ts[cl * 136 + rl + 8]       = __float2half_rn(d[2]);
                Ts[(cl + 1) * 136 + rl + 8] = __float2half_rn(d[3]);
            }
        __syncthreads();
        __half* Vt = (__half*)args.C[blockIdx.z];
        const int a  = t >> 6;               // 0..1
        const int b2 = t & 63;               // 0..63 (m pair index)
        #pragma unroll 8
        for (int ni2 = 0; ni2 < 64; ni2++) {
            const int nl = ni2 * 2 + a;
            uint32_t u = ((uint32_t*)(Ts + nl * 136))[b2];
            *(uint32_t*)(Vt + (long)(n0 + nl) * M_ + m0 + b2 * 2) = u;
        }
    }
}

// ---------------------------------------------------------------------------
// flash_mma: fp16 tensor-core flash attention (causal), fp32 softmax/acc.
// Block = 128 q rows, 8 warps x 16 rows. K-tiles of 64 keys, 4-stage cp.async
// (R15 measured-better flash config). K token-major, V d-major (g_Vt).
// ---------------------------------------------------------------------------
#define FSTR 36                              // 32 pair-cols + 4 pad (uint32)
#define KV_STAGE (2 * 64 * FSTR)             // K + V tiles per stage
#define FNSTAGE 4
#define FLASH_SMEM ((FNSTAGE * KV_STAGE + 128 * FSTR) * 4)   // 92,160 B

__global__ __launch_bounds__(256)
void flash_mma(const __half* __restrict__ Qh, const __half* __restrict__ Kh,
               const __half* __restrict__ Vth, __half* __restrict__ O) {
    uint32_t* smem = smem_u32;
    uint32_t* Ps = smem + FNSTAGE * KV_STAGE; // [128][FSTR] (Q stage / P pairs)

    const int t    = threadIdx.x;
    const int lane = t & 31;
    const int w    = t >> 5;
    const int g    = lane >> 2;
    const int c    = lane & 3;
    const int wm   = w * 16;

    const int qt = (gridDim.x - 1) - blockIdx.x;   // LPT: longest first
    const int h  = blockIdx.y;
    const int b  = blockIdx.z;
    const int q0 = qt * 128;
    const int row0 = q0 + wm + g;
    const int row1 = row0 + 8;

    // ---- stage Q tile (cp.async group 0) ----
    {
        const __half* Qg = Qh + ((long)(b * S_ + q0)) * E_ + h * 64;
        #pragma unroll
        for (int i = 0; i < 4; i++) {
            const int idx = i * 256 + t;     // 0..1023
            const int r = idx >> 3;          // 0..127
            const int seg = idx & 7;         // 8 halves per seg
            cp16(&Ps[r * FSTR + seg * 4], Qg + (long)r * E_ + seg * 8);
        }
        CP_COMMIT();
    }

    const int ktmax = 2 * (qt + 1);

    auto issue_kv = [&](int kt, int bufi) {
        const __half* Kp = Kh + ((long)(b * S_ + kt * 64)) * E_ + h * 64;
        const __half* Vp = Vth + (long)(h * 64) * M_ + b * S_ + kt * 64;
        uint32_t* Kb = smem + bufi * KV_STAGE;
        uint32_t* Vb = Kb + 64 * FSTR;
        #pragma unroll
        for (int i = 0; i < 2; i++) {
            const int idx = i * 256 + t;     // 0..511
            const int r = idx >> 3;          // 0..63
            const int seg = idx & 7;
            cp16(&Kb[r * FSTR + seg * 4], Kp + (long)r * E_ + seg * 8);
            cp16(&Vb[r * FSTR + seg * 4], Vp + (long)r * M_ + seg * 8);
        }
        CP_COMMIT();
    };

    // prologue: up to 3 KV tiles in flight
    issue_kv(0, 0);
    if (ktmax > 1) issue_kv(1, 1);
    if (ktmax > 2) issue_kv(2, 2);

    // wait for Q (groups pending: the issued KV tiles)
    {
        const int kvp = (ktmax > 2) ? 3 : ktmax;   // issued kv groups
        if (kvp == 3)      { CP_WAIT(3); }
        else if (kvp == 2) { CP_WAIT(2); }
        else               { CP_WAIT(1); }
    }
    __syncthreads();

    // Q fragments, pre-scaled by 1/8 (exact in fp16)
    const __half2 sc2 = __float2half2_rn(0.125f);
    uint32_t qa[4][4];
    #pragma unroll
    for (int ks = 0; ks < 4; ks++) {
        #pragma unroll
        for (int j = 0; j < 4; j++) {
            const int row = wm + g + ((j & 1) ? 8 : 0);
            const int cp  = ks * 8 + c + ((j & 2) ? 4 : 0);
            uint32_t u = Ps[row * FSTR + cp];
            __half2 hv = __hmul2(*(__half2*)&u, sc2);
            qa[ks][j] = h2u(hv);
        }
    }

    float accO[8][4];
    #pragma unroll
    for (int i = 0; i < 8; i++)
        #pragma unroll
        for (int j = 0; j < 4; j++) accO[i][j] = 0.f;
    float m0v = -1e30f, m1v = -1e30f, l0 = 0.f, l1 = 0.f;

    int buf = 0;
    for (int kt = 0; kt < ktmax; kt++) {
        const int ks = kt * 64;

        const int rem = ktmax - 1 - kt;      // kv groups pending after kt done
        if (rem >= 2)      { CP_WAIT(2); }
        else if (rem == 1) { CP_WAIT(1); }
        else               { CP_WAIT(0); }
        __syncthreads();                     // tile kt visible; buf[(kt+3)%4] free
        if (kt + 3 < ktmax) issue_kv(kt + 3, (buf + 3) & 3);

        const uint32_t* Kb = smem + buf * KV_STAGE;
        const uint32_t* Vb = Kb + 64 * FSTR;

        if (ks <= q0 + wm + 15) {
            // ---- S = Q K^T ----
            float sc[8][4];
            #pragma unroll
            for (int nt = 0; nt < 8; nt++)
                #pragma unroll
                for (int j = 0; j < 4; j++) sc[nt][j] = 0.f;

            #pragma unroll
            for (int kc = 0; kc < 4; kc++) {
                #pragma unroll
                for (int nt = 0; nt < 8; nt++) {
                    uint32_t b0 = Kb[(nt * 8 + g) * FSTR + kc * 8 + c];
                    uint32_t b1 = Kb[(nt * 8 + g) * FSTR + kc * 8 + c + 4];
                    mma_f16(sc[nt][0], sc[nt][1], sc[nt][2], sc[nt][3],
                            qa[kc][0], qa[kc][1], qa[kc][2], qa[kc][3], b0, b1);
                }
            }

            // ---- causal mask (diagonal-straddling tiles only) ----
            if (ks + 63 > q0 + wm) {
                const int colbase = ks + 2 * c;
                #pragma unroll
                for (int nt = 0; nt < 8; nt++) {
                    const int col = colbase + nt * 8;
                    if (col     > row0) sc[nt][0] = -1e30f;
                    if (col + 1 > row0) sc[nt][1] = -1e30f;
                    if (col     > row1) sc[nt][2] = -1e30f;
                    if (col + 1 > row1) sc[nt][3] = -1e30f;
                }
            }

            // ---- online softmax ----
            float tm0 = -1e30f, tm1 = -1e30f;
            #pragma unroll
            for (int nt = 0; nt < 8; nt++) {
                tm0 = fmaxf(tm0, fmaxf(sc[nt][0], sc[nt][1]));
                tm1 = fmaxf(tm1, fmaxf(sc[nt][2], sc[nt][3]));
            }
            tm0 = fmaxf(tm0, __shfl_xor_sync(0xffffffff, tm0, 1));
            tm0 = fmaxf(tm0, __shfl_xor_sync(0xffffffff, tm0, 2));
            tm1 = fmaxf(tm1, __shfl_xor_sync(0xffffffff, tm1, 1));
            tm1 = fmaxf(tm1, __shfl_xor_sync(0xffffffff, tm1, 2));

            const float mn0 = fmaxf(m0v, tm0);
            const float mn1 = fmaxf(m1v, tm1);
            const float corr0 = __expf(m0v - mn0);
            const float corr1 = __expf(m1v - mn1);

            float ls0 = 0.f, ls1 = 0.f;
            #pragma unroll
            for (int nt = 0; nt < 8; nt++) {
                sc[nt][0] = __expf(sc[nt][0] - mn0);
                sc[nt][1] = __expf(sc[nt][1] - mn0);
                sc[nt][2] = __expf(sc[nt][2] - mn1);
                sc[nt][3] = __expf(sc[nt][3] - mn1);
                ls0 += sc[nt][0] + sc[nt][1];
                ls1 += sc[nt][2] + sc[nt][3];
            }
            ls0 += __shfl_xor_sync(0xffffffff, ls0, 1);
            ls0 += __shfl_xor_sync(0xffffffff, ls0, 2);
            ls1 += __shfl_xor_sync(0xffffffff, ls1, 1);
            ls1 += __shfl_xor_sync(0xffffffff, ls1, 2);

            l0 = l0 * corr0 + ls0;
            l1 = l1 * corr1 + ls1;
            m0v = mn0; m1v = mn1;

            #pragma unroll
            for (int nt = 0; nt < 8; nt++) {
                accO[nt][0] *= corr0; accO[nt][1] *= corr0;
                accO[nt][2] *= corr1; accO[nt][3] *= corr1;
            }

            // ---- P -> half2 pairs in smem (warp-private rows) ----
            __syncwarp();
            #pragma unroll
            for (int nt = 0; nt < 8; nt++) {
                Ps[(wm + g) * FSTR + nt * 4 + c]     = h2u(__floats2half2_rn(sc[nt][0], sc[nt][1]));
                Ps[(wm + g + 8) * FSTR + nt * 4 + c] = h2u(__floats2half2_rn(sc[nt][2], sc[nt][3]));
            }
            __syncwarp();

            // ---- O += P V  (V^T tiles: rows = d, pair-cols = keys) ----
            #pragma unroll
            for (int kc = 0; kc < 4; kc++) {
                uint32_t a0 = Ps[(wm + g) * FSTR + kc * 8 + c];
                uint32_t a1 = Ps[(wm + g + 8) * FSTR + kc * 8 + c];
                uint32_t a2 = Ps[(wm + g) * FSTR + kc * 8 + c + 4];
                uint32_t a3 = Ps[(wm + g + 8) * FSTR + kc * 8 + c + 4];
                #pragma unroll
                for (int nt = 0; nt < 8; nt++) {
                    uint32_t b0 = Vb[(nt * 8 + g) * FSTR + kc * 8 + c];
                    uint32_t b1 = Vb[(nt * 8 + g) * FSTR + kc * 8 + c + 4];
                    mma_f16(accO[nt][0], accO[nt][1], accO[nt][2], accO[nt][3],
                            a0, a1, a2, a3, b0, b1);
                }
            }
        }
        buf = (buf + 1) & 3;
    }

    // ---- epilogue: O as fp16 (feeds final GEMM) ----
    const float inv0 = 1.f / l0;
    const float inv1 = 1.f / l1;
    __half* O0 = O + ((long)(b * S_ + row0)) * E_ + h * 64;
    __half* O1 = O + ((long)(b * S_ + row1)) * E_ + h * 64;
    #pragma unroll
    for (int nt = 0; nt < 8; nt++) {
        *(uint32_t*)(O0 + nt * 8 + 2 * c) =
            h2u(__floats2half2_rn(accO[nt][0] * inv0, accO[nt][1] * inv0));
        *(uint32_t*)(O1 + nt * 8 + 2 * c) =
            h2u(__floats2half2_rn(accO[nt][2] * inv1, accO[nt][3] * inv1));
    }
}

// ---------------------------------------------------------------------------
// Launch
// ---------------------------------------------------------------------------
extern "C" void kernel_launch(void* const* d_in, const int* in_sizes, int n_in,
                              void* d_out, int out_size) {
    const float* X  = nullptr;
    const float* Wm[4] = {nullptr, nullptr, nullptr, nullptr};
    int wcount = 0;
    for (int i = 0; i < n_in; i++) {
        const long sz = in_sizes[i];
        if (sz == (long)M_ * E_) {
            X = (const float*)d_in[i];
        } else if (sz == (long)E_ * E_) {
            if (wcount < 4) Wm[wcount++] = (const float*)d_in[i];
        }
    }
    float* out = (float*)d_out;

    __half *Xp, *Wqp, *Wkp, *Wvp, *Wpp, *Qp, *Kp, *Vtp, *Op;
    cudaGetSymbolAddress((void**)&Xp,  g_X);
    cudaGetSymbolAddress((void**)&Wqp, g_Wq);
    cudaGetSymbolAddress((void**)&Wkp, g_Wk);
    cudaGetSymbolAddress((void**)&Wvp, g_Wv);
    cudaGetSymbolAddress((void**)&Wpp, g_Wp);
    cudaGetSymbolAddress((void**)&Qp,  g_Q);
    cudaGetSymbolAddress((void**)&Kp,  g_K);
    cudaGetSymbolAddress((void**)&Vtp, g_Vt);
    cudaGetSymbolAddress((void**)&Op,  g_O);

    cudaFuncSetAttribute(hgemm_batched,
                         cudaFuncAttributeMaxDynamicSharedMemorySize, GEMM_SMEM);
    cudaFuncSetAttribute(flash_mma,
                         cudaFuncAttributeMaxDynamicSharedMemorySize, FLASH_SMEM);

    // Prepass (1 launch): round all inputs to fp16.
    round_all_k<<<(NTOT + 255) / 256, 256>>>(X, Wm[0], Wm[1], Wm[2], Wm[3],
                                             Xp, Wqp, Wkp, Wvp, Wpp);

    // Fused Q/K/V projections. V written transposed.
    GemmBatch qkv;
    qkv.W[0] = Wqp; qkv.W[1] = Wkp; qkv.W[2] = Wvp;
    qkv.C[0] = Qp;  qkv.C[1] = Kp;  qkv.C[2] = Vtp;
    qkv.mode[0] = 0; qkv.mode[1] = 0; qkv.mode[2] = 1;
    dim3 qkvGrid(E_ / 128, M_ / 128, 3);   // (8, 64, 3)
    hgemm_batched<<<qkvGrid, 128, GEMM_SMEM>>>(Xp, qkv);

    // Attention
    dim3 fGrid(S_ / 128, H_, B_);          // (16, 16, 4)
    flash_mma<<<fGrid, 256, FLASH_SMEM>>>(Qp, Kp, Vtp, Op);

    // Output projection (fp32 out)
    GemmBatch proj;
    proj.W[0] = Wpp; proj.W[1] = Wpp; proj.W[2] = Wpp;
    proj.C[0] = out; proj.C[1] = out; proj.C[2] = out;
    proj.mode[0] = 2; proj.mode[1] = 2; proj.mode[2] = 2;
    dim3 pGrid(E_ / 128, M_ / 128, 1);
    hgemm_batched<<<pGrid, 128, GEMM_SMEM>>>(Op, proj);
}

// round 17
// speedup vs baseline: 1.1084x; 1.0821x over previous
#include <cuda_runtime.h>
#include <cuda_fp16.h>
#include <cstdint>

// Problem constants (fixed by setup_inputs)
#define B_   4
#define S_   2048
#define E_   1024
#define H_   16
#define D_   64
#define M_   (B_ * S_)   // 8192 rows

// Scratch (no allocation allowed). All fp16 (11-bit significand == tf32).
__device__ __half g_X[M_ * E_];
__device__ __half g_Wq[E_ * E_];
__device__ __half g_Wk[E_ * E_];
__device__ __half g_Wv[E_ * E_];
__device__ __half g_Wp[E_ * E_];
__device__ __half g_Q[M_ * E_];
__device__ __half g_K[M_ * E_];
__device__ __half g_Vt[E_ * M_];   // TRANSPOSED: [n = h*64+d][m = b*2048+s]
__device__ __half g_O[M_ * E_];

// Single extern shared declaration for the whole TU.
extern __shared__ uint32_t smem_u32[];

// ---------------------------------------------------------------------------
// helpers
// ---------------------------------------------------------------------------
__device__ __forceinline__ uint32_t h2u(__half2 h) { return *(uint32_t*)&h; }

__device__ __forceinline__ void mma_f16(float& d0, float& d1, float& d2, float& d3,
                                        uint32_t a0, uint32_t a1, uint32_t a2, uint32_t a3,
                                        uint32_t b0, uint32_t b1) {
    asm volatile(
        "mma.sync.aligned.m16n8k16.row.col.f32.f16.f16.f32 "
        "{%0,%1,%2,%3}, {%4,%5,%6,%7}, {%8,%9}, {%0,%1,%2,%3};\n"
        : "+f"(d0), "+f"(d1), "+f"(d2), "+f"(d3)
        : "r"(a0), "r"(a1), "r"(a2), "r"(a3), "r"(b0), "r"(b1));
}

__device__ __forceinline__ void cp16(void* dst_smem, const void* src_gmem) {
    uint32_t d = (uint32_t)__cvta_generic_to_shared(dst_smem);
    asm volatile("cp.async.cg.shared.global [%0], [%1], 16;\n"
                 :: "r"(d), "l"(src_gmem));
}
#define CP_COMMIT()  asm volatile("cp.async.commit_group;\n" ::: "memory")
#define CP_WAIT(n)   asm volatile("cp.async.wait_group %0;\n" :: "n"(n) : "memory")

// ---------------------------------------------------------------------------
// prepass (single launch): round X and the 4 weights to fp16.
// ---------------------------------------------------------------------------
#define NX4  ((M_ * E_) / 4)
#define NW4  ((E_ * E_) / 4)
#define NTOT (NX4 + 4 * NW4)

__global__ void round_all_k(const float* __restrict__ X,
                            const float* __restrict__ W0, const float* __restrict__ W1,
                            const float* __restrict__ W2, const float* __restrict__ W3,
                            __half* __restrict__ dX,
                            __half* __restrict__ dW0, __half* __restrict__ dW1,
                            __half* __restrict__ dW2, __half* __restrict__ dW3) {
    const int i = blockIdx.x * blockDim.x + threadIdx.x;
    if (i >= NTOT) return;
    const float4* src;
    __half* dstb;
    int off;
    if (i < NX4) {
        src = (const float4*)X; dstb = dX; off = i;
    } else {
        const int j = i - NX4;
        const int w = j >> 18;
        off = j & (NW4 - 1);
        const float4* s[4] = {(const float4*)W0, (const float4*)W1,
                              (const float4*)W2, (const float4*)W3};
        __half* d[4] = {dW0, dW1, dW2, dW3};
        src = s[w]; dstb = d[w];
    }
    float4 v = src[off];
    uint2 u;
    u.x = h2u(__floats2half2_rn(v.x, v.y));
    u.y = h2u(__floats2half2_rn(v.z, v.w));
    ((uint2*)dstb)[off] = u;
}

// ---------------------------------------------------------------------------
// Batched fp16 GEMM (4-stage pipeline — best measured config):
// C_z[m,n] = sum_k A[m,k]*W_z[n,k], z=blockIdx.z.
// 128x128 block tile, BK=32 halves, 128 thr (4 warps), warp tile 64x64.
// CP_WAIT(2): two tiles in flight. One __syncthreads per k-tile.
// mode: 0 = half out (Q/K), 1 = half out TRANSPOSED (V), 2 = float out (proj).
// ---------------------------------------------------------------------------
#define SPAD 20                              // 16 pair-cols + 4 pad (uint32)
#define STAGE_W (128 * SPAD)
#define NSTAGE 4
#define GEMM_SMEM (NSTAGE * 2 * STAGE_W * 4) // 81,920 B -> 2 CTAs/SM OK

struct GemmBatch {
    const __half* W[3];
    void* C[3];
    int mode[3];
};

__global__ __launch_bounds__(128, 2)
void hgemm_batched(const __half* __restrict__ A, GemmBatch args) {
    uint32_t* As = smem_u32;                      // [4][128][SPAD]
    uint32_t* Ws = smem_u32 + NSTAGE * STAGE_W;   // [4][128][SPAD]

    const __half* __restrict__ Wg = args.W[blockIdx.z];
    const int mode = args.mode[blockIdx.z];

    const int t    = threadIdx.x;
    const int m0   = blockIdx.y * 128;
    const int n0   = blockIdx.x * 128;
    const int lane = t & 31;
    const int w    = t >> 5;
    const int g    = lane >> 2;
    const int c    = lane & 3;
    const int wm   = (w & 1) * 64;
    const int wn   = (w >> 1) * 64;

    float acc[32][4];
    #pragma unroll
    for (int i = 0; i < 32; i++)
        #pragma unroll
        for (int j = 0; j < 4; j++) acc[i][j] = 0.f;

    const int NT = E_ / 32;                  // 32 k-tiles

    auto issue = [&](int kt, int bufi) {
        const int koff = kt * 32;            // halves
        uint32_t* Ab = As + bufi * STAGE_W;
        uint32_t* Wb = Ws + bufi * STAGE_W;
        #pragma unroll
        for (int i = 0; i < 4; i++) {
            const int idx = i * 128 + t;     // 0..511
            const int r   = idx >> 2;        // 0..127
            const int c16 = idx & 3;         // 0..3 (16B seg = 8 halves)
            cp16(&Ab[r * SPAD + c16 * 4], A  + (long)(m0 + r) * E_ + koff + c16 * 8);
            cp16(&Wb[r * SPAD + c16 * 4], Wg + (long)(n0 + r) * E_ + koff + c16 * 8);
        }
        CP_COMMIT();
    };

    issue(0, 0);
    issue(1, 1);
    issue(2, 2);

    int buf = 0;
    for (int kt = 0; kt < NT; kt++) {
        if (kt + 3 < NT)      { CP_WAIT(2); }
        else if (kt + 2 < NT) { CP_WAIT(1); }
        else                  { CP_WAIT(0); }
        __syncthreads();                     // tile kt visible; buf[(kt+3)%4] free
        if (kt + 3 < NT) issue(kt + 3, (buf + 3) & 3);

        const uint32_t* Ab = As + buf * STAGE_W;
        const uint32_t* Wb = Ws + buf * STAGE_W;

        #pragma unroll
        for (int ks = 0; ks < 2; ks++) {     // 2 x k16 per 32-half tile
            const int k0p = ks * 8;          // pair offset
            uint32_t b[8][2];
            #pragma unroll
            for (int ni = 0; ni < 8; ni++) {
                const int nb = wn + ni * 8;
                b[ni][0] = Wb[(nb + g) * SPAD + k0p + c];
                b[ni][1] = Wb[(nb + g) * SPAD + k0p + c + 4];
            }
            #pragma unroll
            for (int mi = 0; mi < 4; mi++) {
                const int mb = wm + mi * 16;
                uint32_t a0 = Ab[(mb + g) * SPAD + k0p + c];
                uint32_t a1 = Ab[(mb + g + 8) * SPAD + k0p + c];
                uint32_t a2 = Ab[(mb + g) * SPAD + k0p + c + 4];
                uint32_t a3 = Ab[(mb + g + 8) * SPAD + k0p + c + 4];
                #pragma unroll
                for (int ni = 0; ni < 8; ni++) {
                    float* d = acc[mi * 8 + ni];
                    mma_f16(d[0], d[1], d[2], d[3], a0, a1, a2, a3,
                            b[ni][0], b[ni][1]);
                }
            }
        }
        buf = (buf + 1) & 3;
    }

    if (mode == 2) {
        float* C = (float*)args.C[blockIdx.z];
        #pragma unroll
        for (int mi = 0; mi < 4; mi++)
            #pragma unroll
            for (int ni = 0; ni < 8; ni++) {
                float* d = acc[mi * 8 + ni];
                const long r0 = m0 + wm + mi * 16 + g;
                const long col = n0 + wn + ni * 8 + 2 * c;
                *(float2*)(C + r0 * E_ + col)       = make_float2(d[0], d[1]);
                *(float2*)(C + (r0 + 8) * E_ + col) = make_float2(d[2], d[3]);
            }
    } else if (mode == 0) {
        __half* C = (__half*)args.C[blockIdx.z];
        #pragma unroll
        for (int mi = 0; mi < 4; mi++)
            #pragma unroll
            for (int ni = 0; ni < 8; ni++) {
                float* d = acc[mi * 8 + ni];
                const long r0 = m0 + wm + mi * 16 + g;
                const long col = n0 + wn + ni * 8 + 2 * c;
                *(uint32_t*)(C + r0 * E_ + col)       = h2u(__floats2half2_rn(d[0], d[1]));
                *(uint32_t*)(C + (r0 + 8) * E_ + col) = h2u(__floats2half2_rn(d[2], d[3]));
            }
    } else {
        // V: transpose through SMEM, write g_Vt[n][m] coalesced.
        __syncthreads();                     // mainloop smem reads done
        __half* Ts = (__half*)smem_u32;      // [128 n][136 m] halves
        #pragma unroll
        for (int mi = 0; mi < 4; mi++)
            #pragma unroll
            for (int ni = 0; ni < 8; ni++) {
                float* d = acc[mi * 8 + ni];
                const int rl = wm + mi * 16 + g;
                const int cl = wn + ni * 8 + 2 * c;
                Ts[cl * 136 + rl]           = __float2half_rn(d[0]);
                Ts[(cl + 1) * 136 + rl]     = __float2half_rn(d[1]);
                Ts[cl * 136 + rl + 8]       = __float2half_rn(d[2]);
                Ts[(cl + 1) * 136 + rl + 8] = __float2half_rn(d[3]);
            }
        __syncthreads();
        __half* Vt = (__half*)args.C[blockIdx.z];
        const int a  = t >> 6;               // 0..1
        const int b2 = t & 63;               // 0..63 (m pair index)
        #pragma unroll 8
        for (int ni2 = 0; ni2 < 64; ni2++) {
            const int nl = ni2 * 2 + a;
            uint32_t u = ((uint32_t*)(Ts + nl * 136))[b2];
            *(uint32_t*)(Vt + (long)(n0 + nl) * M_ + m0 + b2 * 2) = u;
        }
    }
}

// ---------------------------------------------------------------------------
// flash_mma: fp16 tensor-core flash attention (causal), fp32 softmax/acc.
// Block = 128 q rows, 8 warps x 16 rows. K-tiles of 64 keys, 4-stage cp.async.
// GLOBAL LPT grid: blockIdx.x = (h,b) [64], blockIdx.y = reversed q-tile [16]
// -> launch order emits ALL longest blocks first across every (h,b).
// ---------------------------------------------------------------------------
#define FSTR 36                              // 32 pair-cols + 4 pad (uint32)
#define KV_STAGE (2 * 64 * FSTR)             // K + V tiles per stage
#define FNSTAGE 4
#define FLASH_SMEM ((FNSTAGE * KV_STAGE + 128 * FSTR) * 4)   // 92,160 B

__global__ __launch_bounds__(256)
void flash_mma(const __half* __restrict__ Qh, const __half* __restrict__ Kh,
               const __half* __restrict__ Vth, __half* __restrict__ O) {
    uint32_t* smem = smem_u32;
    uint32_t* Ps = smem + FNSTAGE * KV_STAGE; // [128][FSTR] (Q stage / P pairs)

    const int t    = threadIdx.x;
    const int lane = t & 31;
    const int w    = t >> 5;
    const int g    = lane >> 2;
    const int c    = lane & 3;
    const int wm   = w * 16;

    const int hb = blockIdx.x;                     // 0..63
    const int h  = hb & (H_ - 1);
    const int b  = hb >> 4;
    const int qt = (gridDim.y - 1) - blockIdx.y;   // global LPT: longest first
    const int q0 = qt * 128;
    const int row0 = q0 + wm + g;
    const int row1 = row0 + 8;

    // ---- stage Q tile (cp.async group 0) ----
    {
        const __half* Qg = Qh + ((long)(b * S_ + q0)) * E_ + h * 64;
        #pragma unroll
        for (int i = 0; i < 4; i++) {
            const int idx = i * 256 + t;     // 0..1023
            const int r = idx >> 3;          // 0..127
            const int seg = idx & 7;         // 8 halves per seg
            cp16(&Ps[r * FSTR + seg * 4], Qg + (long)r * E_ + seg * 8);
        }
        CP_COMMIT();
    }

    const int ktmax = 2 * (qt + 1);

    auto issue_kv = [&](int kt, int bufi) {
        const __half* Kp = Kh + ((long)(b * S_ + kt * 64)) * E_ + h * 64;
        const __half* Vp = Vth + (long)(h * 64) * M_ + b * S_ + kt * 64;
        uint32_t* Kb = smem + bufi * KV_STAGE;
        uint32_t* Vb = Kb + 64 * FSTR;
        #pragma unroll
        for (int i = 0; i < 2; i++) {
            const int idx = i * 256 + t;     // 0..511
            const int r = idx >> 3;          // 0..63
            const int seg = idx & 7;
            cp16(&Kb[r * FSTR + seg * 4], Kp + (long)r * E_ + seg * 8);
            cp16(&Vb[r * FSTR + seg * 4], Vp + (long)r * M_ + seg * 8);
        }
        CP_COMMIT();
    };

    // prologue: up to 3 KV tiles in flight
    issue_kv(0, 0);
    if (ktmax > 1) issue_kv(1, 1);
    if (ktmax > 2) issue_kv(2, 2);

    // wait for Q (groups pending: the issued KV tiles)
    {
        const int kvp = (ktmax > 2) ? 3 : ktmax;   // issued kv groups
        if (kvp == 3)      { CP_WAIT(3); }
        else if (kvp == 2) { CP_WAIT(2); }
        else               { CP_WAIT(1); }
    }
    __syncthreads();

    // Q fragments, pre-scaled by 1/8 (exact in fp16)
    const __half2 sc2 = __float2half2_rn(0.125f);
    uint32_t qa[4][4];
    #pragma unroll
    for (int ks = 0; ks < 4; ks++) {
        #pragma unroll
        for (int j = 0; j < 4; j++) {
            const int row = wm + g + ((j & 1) ? 8 : 0);
            const int cp  = ks * 8 + c + ((j & 2) ? 4 : 0);
            uint32_t u = Ps[row * FSTR + cp];
            __half2 hv = __hmul2(*(__half2*)&u, sc2);
            qa[ks][j] = h2u(hv);
        }
    }

    float accO[8][4];
    #pragma unroll
    for (int i = 0; i < 8; i++)
        #pragma unroll
        for (int j = 0; j < 4; j++) accO[i][j] = 0.f;
    float m0v = -1e30f, m1v = -1e30f, l0 = 0.f, l1 = 0.f;

    int buf = 0;
    for (int kt = 0; kt < ktmax; kt++) {
        const int ks = kt * 64;

        const int rem = ktmax - 1 - kt;      // kv groups pending after kt done
        if (rem >= 2)      { CP_WAIT(2); }
        else if (rem == 1) { CP_WAIT(1); }
        else               { CP_WAIT(0); }
        __syncthreads();                     // tile kt visible; buf[(kt+3)%4] free
        if (kt + 3 < ktmax) issue_kv(kt + 3, (buf + 3) & 3);

        const uint32_t* Kb = smem + buf * KV_STAGE;
        const uint32_t* Vb = Kb + 64 * FSTR;

        if (ks <= q0 + wm + 15) {
            // ---- S = Q K^T ----
            float sc[8][4];
            #pragma unroll
            for (int nt = 0; nt < 8; nt++)
                #pragma unroll
                for (int j = 0; j < 4; j++) sc[nt][j] = 0.f;

            #pragma unroll
            for (int kc = 0; kc < 4; kc++) {
                #pragma unroll
                for (int nt = 0; nt < 8; nt++) {
                    uint32_t b0 = Kb[(nt * 8 + g) * FSTR + kc * 8 + c];
                    uint32_t b1 = Kb[(nt * 8 + g) * FSTR + kc * 8 + c + 4];
                    mma_f16(sc[nt][0], sc[nt][1], sc[nt][2], sc[nt][3],
                            qa[kc][0], qa[kc][1], qa[kc][2], qa[kc][3], b0, b1);
                }
            }

            // ---- causal mask (diagonal-straddling tiles only) ----
            if (ks + 63 > q0 + wm) {
                const int colbase = ks + 2 * c;
                #pragma unroll
                for (int nt = 0; nt < 8; nt++) {
                    const int col = colbase + nt * 8;
                    if (col     > row0) sc[nt][0] = -1e30f;
                    if (col + 1 > row0) sc[nt][1] = -1e30f;
                    if (col     > row1) sc[nt][2] = -1e30f;
                    if (col + 1 > row1) sc[nt][3] = -1e30f;
                }
            }

            // ---- online softmax ----
            float tm0 = -1e30f, tm1 = -1e30f;
            #pragma unroll
            for (int nt = 0; nt < 8; nt++) {
                tm0 = fmaxf(tm0, fmaxf(sc[nt][0], sc[nt][1]));
                tm1 = fmaxf(tm1, fmaxf(sc[nt][2], sc[nt][3]));
            }
            tm0 = fmaxf(tm0, __shfl_xor_sync(0xffffffff, tm0, 1));
            tm0 = fmaxf(tm0, __shfl_xor_sync(0xffffffff, tm0, 2));
            tm1 = fmaxf(tm1, __shfl_xor_sync(0xffffffff, tm1, 1));
            tm1 = fmaxf(tm1, __shfl_xor_sync(0xffffffff, tm1, 2));

            const float mn0 = fmaxf(m0v, tm0);
            const float mn1 = fmaxf(m1v, tm1);
            const float corr0 = __expf(m0v - mn0);
            const float corr1 = __expf(m1v - mn1);

            float ls0 = 0.f, ls1 = 0.f;
            #pragma unroll
            for (int nt = 0; nt < 8; nt++) {
                sc[nt][0] = __expf(sc[nt][0] - mn0);
                sc[nt][1] = __expf(sc[nt][1] - mn0);
                sc[nt][2] = __expf(sc[nt][2] - mn1);
                sc[nt][3] = __expf(sc[nt][3] - mn1);
                ls0 += sc[nt][0] + sc[nt][1];
                ls1 += sc[nt][2] + sc[nt][3];
            }
            ls0 += __shfl_xor_sync(0xffffffff, ls0, 1);
            ls0 += __shfl_xor_sync(0xffffffff, ls0, 2);
            ls1 += __shfl_xor_sync(0xffffffff, ls1, 1);
            ls1 += __shfl_xor_sync(0xffffffff, ls1, 2);

            l0 = l0 * corr0 + ls0;
            l1 = l1 * corr1 + ls1;
            m0v = mn0; m1v = mn1;

            #pragma unroll
            for (int nt = 0; nt < 8; nt++) {
                accO[nt][0] *= corr0; accO[nt][1] *= corr0;
                accO[nt][2] *= corr1; accO[nt][3] *= corr1;
            }

            // ---- P -> half2 pairs in smem (warp-private rows) ----
            __syncwarp();
            #pragma unroll
            for (int nt = 0; nt < 8; nt++) {
                Ps[(wm + g) * FSTR + nt * 4 + c]     = h2u(__floats2half2_rn(sc[nt][0], sc[nt][1]));
                Ps[(wm + g + 8) * FSTR + nt * 4 + c] = h2u(__floats2half2_rn(sc[nt][2], sc[nt][3]));
            }
            __syncwarp();

            // ---- O += P V  (V^T tiles: rows = d, pair-cols = keys) ----
            #pragma unroll
            for (int kc = 0; kc < 4; kc++) {
                uint32_t a0 = Ps[(wm + g) * FSTR + kc * 8 + c];
                uint32_t a1 = Ps[(wm + g + 8) * FSTR + kc * 8 + c];
                uint32_t a2 = Ps[(wm + g) * FSTR + kc * 8 + c + 4];
                uint32_t a3 = Ps[(wm + g + 8) * FSTR + kc * 8 + c + 4];
                #pragma unroll
                for (int nt = 0; nt < 8; nt++) {
                    uint32_t b0 = Vb[(nt * 8 + g) * FSTR + kc * 8 + c];
                    uint32_t b1 = Vb[(nt * 8 + g) * FSTR + kc * 8 + c + 4];
                    mma_f16(accO[nt][0], accO[nt][1], accO[nt][2], accO[nt][3],
                            a0, a1, a2, a3, b0, b1);
                }
            }
        }
        buf = (buf + 1) & 3;
    }

    // ---- epilogue: O as fp16 (feeds final GEMM) ----
    const float inv0 = 1.f / l0;
    const float inv1 = 1.f / l1;
    __half* O0 = O + ((long)(b * S_ + row0)) * E_ + h * 64;
    __half* O1 = O + ((long)(b * S_ + row1)) * E_ + h * 64;
    #pragma unroll
    for (int nt = 0; nt < 8; nt++) {
        *(uint32_t*)(O0 + nt * 8 + 2 * c) =
            h2u(__floats2half2_rn(accO[nt][0] * inv0, accO[nt][1] * inv0));
        *(uint32_t*)(O1 + nt * 8 + 2 * c) =
            h2u(__floats2half2_rn(accO[nt][2] * inv1, accO[nt][3] * inv1));
    }
}

// ---------------------------------------------------------------------------
// Launch
// ---------------------------------------------------------------------------
extern "C" void kernel_launch(void* const* d_in, const int* in_sizes, int n_in,
                              void* d_out, int out_size) {
    const float* X  = nullptr;
    const float* Wm[4] = {nullptr, nullptr, nullptr, nullptr};
    int wcount = 0;
    for (int i = 0; i < n_in; i++) {
        const long sz = in_sizes[i];
        if (sz == (long)M_ * E_) {
            X = (const float*)d_in[i];
        } else if (sz == (long)E_ * E_) {
            if (wcount < 4) Wm[wcount++] = (const float*)d_in[i];
        }
    }
    float* out = (float*)d_out;

    __half *Xp, *Wqp, *Wkp, *Wvp, *Wpp, *Qp, *Kp, *Vtp, *Op;
    cudaGetSymbolAddress((void**)&Xp,  g_X);
    cudaGetSymbolAddress((void**)&Wqp, g_Wq);
    cudaGetSymbolAddress((void**)&Wkp, g_Wk);
    cudaGetSymbolAddress((void**)&Wvp, g_Wv);
    cudaGetSymbolAddress((void**)&Wpp, g_Wp);
    cudaGetSymbolAddress((void**)&Qp,  g_Q);
    cudaGetSymbolAddress((void**)&Kp,  g_K);
    cudaGetSymbolAddress((void**)&Vtp, g_Vt);
    cudaGetSymbolAddress((void**)&Op,  g_O);

    cudaFuncSetAttribute(hgemm_batched,
                         cudaFuncAttributeMaxDynamicSharedMemorySize, GEMM_SMEM);
    cudaFuncSetAttribute(flash_mma,
                         cudaFuncAttributeMaxDynamicSharedMemorySize, FLASH_SMEM);

    // Prepass (1 launch): round all inputs to fp16.
    round_all_k<<<(NTOT + 255) / 256, 256>>>(X, Wm[0], Wm[1], Wm[2], Wm[3],
                                             Xp, Wqp, Wkp, Wvp, Wpp);

    // Fused Q/K/V projections. V written transposed.
    GemmBatch qkv;
    qkv.W[0] = Wqp; qkv.W[1] = Wkp; qkv.W[2] = Wvp;
    qkv.C[0] = Qp;  qkv.C[1] = Kp;  qkv.C[2] = Vtp;
    qkv.mode[0] = 0; qkv.mode[1] = 0; qkv.mode[2] = 1;
    dim3 qkvGrid(E_ / 128, M_ / 128, 3);   // (8, 64, 3)
    hgemm_batched<<<qkvGrid, 128, GEMM_SMEM>>>(Xp, qkv);

    // Attention — global LPT grid: x = (h,b), y = reversed q-tile.
    dim3 fGrid(H_ * B_, S_ / 128, 1);      // (64, 16, 1)
    flash_mma<<<fGrid, 256, FLASH_SMEM>>>(Qp, Kp, Vtp, Op);

    // Output projection (fp32 out)
    GemmBatch proj;
    proj.W[0] = Wpp; proj.W[1] = Wpp; proj.W[2] = Wpp;
    proj.C[0] = out; proj.C[1] = out; proj.C[2] = out;
    proj.mode[0] = 2; proj.mode[1] = 2; proj.mode[2] = 2;
    dim3 pGrid(E_ / 128, M_ / 128, 1);
    hgemm_batched<<<pGrid, 128, GEMM_SMEM>>>(Op, proj);
}